// round 2
// baseline (speedup 1.0000x reference)
#include <cuda_runtime.h>

#define MAX_NODES 100000
#define MAX_EDGES 1600000
#define F 128

// Scratch (__device__ globals: allocation-free rule)
__device__ __align__(16) float g_agg1[(size_t)MAX_NODES * F];   // 51.2 MB
__device__ __align__(16) float g_t2[MAX_NODES * 2];
__device__ float g_ninv_out[MAX_NODES];
__device__ float g_ninv_in[MAX_NODES];
__device__ int g_dego[MAX_NODES];
__device__ int g_degi[MAX_NODES];
__device__ int g_rowoff[MAX_NODES];
__device__ int g_cursor[MAX_NODES];
__device__ int g_csr[MAX_EDGES];      // src index per in-edge, grouped by dst

// ---------------------------------------------------------------------------
__global__ void k_zero(int n_nodes) {
    int i = blockIdx.x * blockDim.x + threadIdx.x;
    if (i < n_nodes) { g_dego[i] = 0; g_degi[i] = 0; }
}

__global__ void k_deg(const int* __restrict__ src, const int* __restrict__ dst,
                      int n_edges) {
    int e = blockIdx.x * blockDim.x + threadIdx.x;
    if (e >= n_edges) return;
    atomicAdd(&g_dego[src[e]], 1);
    atomicAdd(&g_degi[dst[e]], 1);
}

__global__ void k_ninv(int n_nodes) {
    int i = blockIdx.x * blockDim.x + threadIdx.x;
    if (i >= n_nodes) return;
    int dof = g_dego[i], din = g_degi[i];
    g_ninv_out[i] = dof > 0 ? rsqrtf((float)dof) : 0.f;
    g_ninv_in[i]  = din > 0 ? rsqrtf((float)din) : 0.f;
}

// Single-block exclusive scan of g_degi -> g_rowoff (and g_cursor copy)
__global__ void k_scan(int n_nodes) {
    __shared__ int part[1024];
    int tid = threadIdx.x;
    int chunk = (n_nodes + 1023) >> 10;
    int lo = tid * chunk;
    int hi = min(lo + chunk, n_nodes);
    int s = 0;
    for (int i = lo; i < hi; i++) s += g_degi[i];
    part[tid] = s;
    __syncthreads();
    for (int off = 1; off < 1024; off <<= 1) {
        int v = (tid >= off) ? part[tid - off] : 0;
        __syncthreads();
        part[tid] += v;
        __syncthreads();
    }
    int base = tid ? part[tid - 1] : 0;
    for (int i = lo; i < hi; i++) {
        g_rowoff[i] = base;
        g_cursor[i] = base;
        base += g_degi[i];
    }
}

__global__ void k_scatter(const int* __restrict__ src, const int* __restrict__ dst,
                          int n_edges) {
    int e = blockIdx.x * blockDim.x + threadIdx.x;
    if (e >= n_edges) return;
    int d = dst[e];
    int pos = atomicAdd(&g_cursor[d], 1);
    g_csr[pos] = src[e];
}

// ---------------------------------------------------------------------------
// Layer-1 pull aggregation: one warp per dst node.
// agg1[v] = sum over in-edges (src s): x[s] * ninv_out[s]
__global__ void k_pull1(const float* __restrict__ x, int n_nodes) {
    int v = (blockIdx.x * blockDim.x + threadIdx.x) >> 5;
    int lane = threadIdx.x & 31;
    if (v >= n_nodes) return;
    int beg = g_rowoff[v];
    int end = beg + g_degi[v];
    const float4* x4 = (const float4*)x;
    float4 acc = make_float4(0.f, 0.f, 0.f, 0.f);
    int j = beg;
    for (; j + 1 < end; j += 2) {
        int s0 = __ldg(g_csr + j);
        int s1 = __ldg(g_csr + j + 1);
        float c0 = g_ninv_out[s0];
        float c1 = g_ninv_out[s1];
        float4 a = __ldg(x4 + (size_t)s0 * (F / 4) + lane);
        float4 b = __ldg(x4 + (size_t)s1 * (F / 4) + lane);
        acc.x = fmaf(a.x, c0, acc.x); acc.y = fmaf(a.y, c0, acc.y);
        acc.z = fmaf(a.z, c0, acc.z); acc.w = fmaf(a.w, c0, acc.w);
        acc.x = fmaf(b.x, c1, acc.x); acc.y = fmaf(b.y, c1, acc.y);
        acc.z = fmaf(b.z, c1, acc.z); acc.w = fmaf(b.w, c1, acc.w);
    }
    if (j < end) {
        int s0 = __ldg(g_csr + j);
        float c0 = g_ninv_out[s0];
        float4 a = __ldg(x4 + (size_t)s0 * (F / 4) + lane);
        acc.x = fmaf(a.x, c0, acc.x); acc.y = fmaf(a.y, c0, acc.y);
        acc.z = fmaf(a.z, c0, acc.z); acc.w = fmaf(a.w, c0, acc.w);
    }
    ((float4*)g_agg1)[(size_t)v * (F / 4) + lane] = acc;
}

// ---------------------------------------------------------------------------
// Fused: h = relu(agg1 @ W1 * ninv_in + b1); t2 = (h * ninv_out) @ W2
// 256 threads, 64 rows/block. Thread (cg=tid&31, rg=tid>>5): 8 rows x 4 cols.
__global__ void __launch_bounds__(256)
k_gemm_fused(const float* __restrict__ W1, const float* __restrict__ b1,
             const float* __restrict__ W2, int n_nodes) {
    __shared__ float sW[64 * F];     // 32 KB (K-half of W1)
    __shared__ float sX[64][64];     // 16 KB (64 rows, K-half)

    int tid = threadIdx.x;
    int cg = tid & 31;        // cols 4*cg .. 4*cg+3
    int rg = tid >> 5;        // rows rg*8 .. rg*8+7 (warp-uniform)
    int row0 = blockIdx.x * 64;

    float acc[8][4];
#pragma unroll
    for (int i = 0; i < 8; i++)
#pragma unroll
        for (int c = 0; c < 4; c++) acc[i][c] = 0.f;

    for (int half = 0; half < 2; half++) {
        const float4* Wsrc = (const float4*)(W1 + half * 64 * F);
        for (int j = tid; j < 2048; j += 256)
            ((float4*)sW)[j] = __ldg(Wsrc + j);
        for (int j = tid; j < 1024; j += 256) {
            int r = j >> 4, c4 = j & 15;
            int row = row0 + r;
            float4 v = make_float4(0.f, 0.f, 0.f, 0.f);
            if (row < n_nodes)
                v = *((const float4*)(g_agg1 + (size_t)row * F + half * 64) + c4);
            ((float4*)&sX[r][0])[c4] = v;
        }
        __syncthreads();
#pragma unroll
        for (int k4 = 0; k4 < 64; k4 += 4) {
            float4 w0 = ((const float4*)(sW + (k4 + 0) * F))[cg];
            float4 w1 = ((const float4*)(sW + (k4 + 1) * F))[cg];
            float4 w2 = ((const float4*)(sW + (k4 + 2) * F))[cg];
            float4 w3 = ((const float4*)(sW + (k4 + 3) * F))[cg];
#pragma unroll
            for (int i = 0; i < 8; i++) {
                float4 xv = *(const float4*)&sX[rg * 8 + i][k4];
                acc[i][0] = fmaf(xv.x, w0.x, acc[i][0]);
                acc[i][1] = fmaf(xv.x, w0.y, acc[i][1]);
                acc[i][2] = fmaf(xv.x, w0.z, acc[i][2]);
                acc[i][3] = fmaf(xv.x, w0.w, acc[i][3]);
                acc[i][0] = fmaf(xv.y, w1.x, acc[i][0]);
                acc[i][1] = fmaf(xv.y, w1.y, acc[i][1]);
                acc[i][2] = fmaf(xv.y, w1.z, acc[i][2]);
                acc[i][3] = fmaf(xv.y, w1.w, acc[i][3]);
                acc[i][0] = fmaf(xv.z, w2.x, acc[i][0]);
                acc[i][1] = fmaf(xv.z, w2.y, acc[i][1]);
                acc[i][2] = fmaf(xv.z, w2.z, acc[i][2]);
                acc[i][3] = fmaf(xv.z, w2.w, acc[i][3]);
                acc[i][0] = fmaf(xv.w, w3.x, acc[i][0]);
                acc[i][1] = fmaf(xv.w, w3.y, acc[i][1]);
                acc[i][2] = fmaf(xv.w, w3.z, acc[i][2]);
                acc[i][3] = fmaf(xv.w, w3.w, acc[i][3]);
            }
        }
        __syncthreads();
    }

    // Epilogue: relu + norms, project to 2 cols of W2, warp-reduce -> g_t2
    float w2a[4], w2b[4], bb[4];
#pragma unroll
    for (int c = 0; c < 4; c++) {
        int col = cg * 4 + c;
        bb[c]  = __ldg(b1 + col);
        w2a[c] = __ldg(W2 + col * 2);
        w2b[c] = __ldg(W2 + col * 2 + 1);
    }
#pragma unroll
    for (int i = 0; i < 8; i++) {
        int row = row0 + rg * 8 + i;
        bool valid = row < n_nodes;
        int rr = valid ? row : 0;
        float ni = g_ninv_in[rr];
        float no = g_ninv_out[rr];
        float p0 = 0.f, p1 = 0.f;
#pragma unroll
        for (int c = 0; c < 4; c++) {
            float h = fmaf(acc[i][c], ni, bb[c]);
            h = fmaxf(h, 0.f) * no;
            p0 = fmaf(h, w2a[c], p0);
            p1 = fmaf(h, w2b[c], p1);
        }
#pragma unroll
        for (int off = 16; off; off >>= 1) {
            p0 += __shfl_xor_sync(0xffffffffu, p0, off);
            p1 += __shfl_xor_sync(0xffffffffu, p1, off);
        }
        if (cg == 0 && valid) {
            g_t2[row * 2]     = p0;
            g_t2[row * 2 + 1] = p1;
        }
    }
}

// ---------------------------------------------------------------------------
// Layer-2 pull: one warp per dst node, lanes strided over in-edges.
// out[v] = ninv_in[v] * sum t2[src] + b2
__global__ void k_pull2(const float* __restrict__ b2, float* __restrict__ out,
                        int n_nodes) {
    int v = (blockIdx.x * blockDim.x + threadIdx.x) >> 5;
    int lane = threadIdx.x & 31;
    if (v >= n_nodes) return;
    int beg = g_rowoff[v];
    int end = beg + g_degi[v];
    float px = 0.f, py = 0.f;
    for (int j = beg + lane; j < end; j += 32) {
        int s = __ldg(g_csr + j);
        float2 t = ((const float2*)g_t2)[s];
        px += t.x; py += t.y;
    }
#pragma unroll
    for (int off = 16; off; off >>= 1) {
        px += __shfl_xor_sync(0xffffffffu, px, off);
        py += __shfl_xor_sync(0xffffffffu, py, off);
    }
    if (lane == 0) {
        float ni = g_ninv_in[v];
        float2 o;
        o.x = fmaf(px, ni, __ldg(b2));
        o.y = fmaf(py, ni, __ldg(b2 + 1));
        ((float2*)out)[v] = o;
    }
}

// ---------------------------------------------------------------------------
extern "C" void kernel_launch(void* const* d_in, const int* in_sizes, int n_in,
                              void* d_out, int out_size) {
    const float* x  = (const float*)d_in[0];
    const float* W1 = (const float*)d_in[1];
    const float* b1 = (const float*)d_in[2];
    const float* W2 = (const float*)d_in[3];
    const float* b2 = (const float*)d_in[4];
    const int* src  = (const int*)d_in[5];
    const int* dst  = (const int*)d_in[6];
    int n_nodes = in_sizes[0] / F;
    int n_edges = in_sizes[5];

    int nbN = (n_nodes + 255) / 256;
    int nbE = (n_edges + 255) / 256;
    int nbW = (n_nodes * 32 + 255) / 256;   // warp per node

    k_zero<<<nbN, 256>>>(n_nodes);
    k_deg<<<nbE, 256>>>(src, dst, n_edges);
    k_ninv<<<nbN, 256>>>(n_nodes);
    k_scan<<<1, 1024>>>(n_nodes);
    k_scatter<<<nbE, 256>>>(src, dst, n_edges);
    k_pull1<<<nbW, 256>>>(x, n_nodes);
    k_gemm_fused<<<(n_nodes + 63) / 64, 256>>>(W1, b1, W2, n_nodes);
    k_pull2<<<nbW, 256>>>(b2, (float*)d_out, n_nodes);
}

// round 3
// speedup vs baseline: 1.6943x; 1.6943x over previous
#include <cuda_runtime.h>

#define MAX_NODES 100000
#define MAX_EDGES 1600000
#define F 128
#define SCAN_CHUNK 256
#define MAX_SCAN_BLOCKS 512   // ceil(100000/256) = 391

// Scratch (__device__ globals: allocation-free rule)
__device__ __align__(16) float g_agg1[(size_t)MAX_NODES * F];   // 51.2 MB
__device__ __align__(16) float g_t2[MAX_NODES * 2];
__device__ float g_ninv_out[MAX_NODES];
__device__ float g_ninv_in[MAX_NODES];
__device__ int g_dego[MAX_NODES];
__device__ int g_degi[MAX_NODES];
__device__ int g_rowoff[MAX_NODES];
__device__ int g_cursor[MAX_NODES];
__device__ int g_csr[MAX_EDGES];      // src index per in-edge, grouped by dst
__device__ int g_bsum[MAX_SCAN_BLOCKS];
__device__ int g_boff[MAX_SCAN_BLOCKS];

// ---------------------------------------------------------------------------
__global__ void k_zero(int n_nodes) {
    int i = blockIdx.x * blockDim.x + threadIdx.x;
    if (i < n_nodes) { g_dego[i] = 0; g_degi[i] = 0; }
}

__global__ void k_deg(const int* __restrict__ src, const int* __restrict__ dst,
                      int n_edges) {
    int e = blockIdx.x * blockDim.x + threadIdx.x;
    if (e >= n_edges) return;
    atomicAdd(&g_dego[src[e]], 1);
    atomicAdd(&g_degi[dst[e]], 1);
}

__global__ void k_ninv(int n_nodes) {
    int i = blockIdx.x * blockDim.x + threadIdx.x;
    if (i >= n_nodes) return;
    int dof = g_dego[i], din = g_degi[i];
    g_ninv_out[i] = dof > 0 ? rsqrtf((float)dof) : 0.f;
    g_ninv_in[i]  = din > 0 ? rsqrtf((float)din) : 0.f;
}

// ---------------------------------------------------------------------------
// 3-phase parallel exclusive scan of g_degi -> g_rowoff / g_cursor
// Phase 1: per-block sums
__global__ void k_scan1(int n_nodes) {
    int i = blockIdx.x * SCAN_CHUNK + threadIdx.x;
    int v = (i < n_nodes) ? g_degi[i] : 0;
#pragma unroll
    for (int off = 16; off; off >>= 1)
        v += __shfl_xor_sync(0xffffffffu, v, off);
    __shared__ int ws[8];
    if ((threadIdx.x & 31) == 0) ws[threadIdx.x >> 5] = v;
    __syncthreads();
    if (threadIdx.x == 0) {
        int s = 0;
#pragma unroll
        for (int w = 0; w < 8; w++) s += ws[w];
        g_bsum[blockIdx.x] = s;
    }
}

// Phase 2: single block scans the (<=512) block sums (exclusive)
__global__ void k_scan2(int n_blocks) {
    __shared__ int part[MAX_SCAN_BLOCKS];
    int tid = threadIdx.x;
    part[tid] = (tid < n_blocks) ? g_bsum[tid] : 0;
    __syncthreads();
#pragma unroll
    for (int off = 1; off < MAX_SCAN_BLOCKS; off <<= 1) {
        int v = (tid >= off) ? part[tid - off] : 0;
        __syncthreads();
        part[tid] += v;
        __syncthreads();
    }
    if (tid < n_blocks) g_boff[tid] = tid ? part[tid - 1] : 0;
}

// Phase 3: per-block exclusive scan + block offset
__global__ void k_scan3(int n_nodes) {
    __shared__ int part[SCAN_CHUNK];
    int tid = threadIdx.x;
    int i = blockIdx.x * SCAN_CHUNK + tid;
    int mine = (i < n_nodes) ? g_degi[i] : 0;
    part[tid] = mine;
    __syncthreads();
#pragma unroll
    for (int off = 1; off < SCAN_CHUNK; off <<= 1) {
        int v = (tid >= off) ? part[tid - off] : 0;
        __syncthreads();
        part[tid] += v;
        __syncthreads();
    }
    if (i < n_nodes) {
        int excl = g_boff[blockIdx.x] + part[tid] - mine;
        g_rowoff[i] = excl;
        g_cursor[i] = excl;
    }
}

__global__ void k_scatter(const int* __restrict__ src, const int* __restrict__ dst,
                          int n_edges) {
    int e = blockIdx.x * blockDim.x + threadIdx.x;
    if (e >= n_edges) return;
    int d = dst[e];
    int pos = atomicAdd(&g_cursor[d], 1);
    g_csr[pos] = src[e];
}

// ---------------------------------------------------------------------------
// Layer-1 pull aggregation: one warp per dst node, 4 edges in flight.
__global__ void k_pull1(const float* __restrict__ x, int n_nodes) {
    int v = (blockIdx.x * blockDim.x + threadIdx.x) >> 5;
    int lane = threadIdx.x & 31;
    if (v >= n_nodes) return;
    int beg = g_rowoff[v];
    int end = beg + g_degi[v];
    const float4* x4 = (const float4*)x;
    float4 acc = make_float4(0.f, 0.f, 0.f, 0.f);
    int j = beg;
    for (; j + 3 < end; j += 4) {
        int s0 = __ldg(g_csr + j);
        int s1 = __ldg(g_csr + j + 1);
        int s2 = __ldg(g_csr + j + 2);
        int s3 = __ldg(g_csr + j + 3);
        float c0 = __ldg(g_ninv_out + s0);
        float c1 = __ldg(g_ninv_out + s1);
        float c2 = __ldg(g_ninv_out + s2);
        float c3 = __ldg(g_ninv_out + s3);
        float4 a = __ldg(x4 + (size_t)s0 * (F / 4) + lane);
        float4 b = __ldg(x4 + (size_t)s1 * (F / 4) + lane);
        float4 c = __ldg(x4 + (size_t)s2 * (F / 4) + lane);
        float4 d = __ldg(x4 + (size_t)s3 * (F / 4) + lane);
        acc.x = fmaf(a.x, c0, acc.x); acc.y = fmaf(a.y, c0, acc.y);
        acc.z = fmaf(a.z, c0, acc.z); acc.w = fmaf(a.w, c0, acc.w);
        acc.x = fmaf(b.x, c1, acc.x); acc.y = fmaf(b.y, c1, acc.y);
        acc.z = fmaf(b.z, c1, acc.z); acc.w = fmaf(b.w, c1, acc.w);
        acc.x = fmaf(c.x, c2, acc.x); acc.y = fmaf(c.y, c2, acc.y);
        acc.z = fmaf(c.z, c2, acc.z); acc.w = fmaf(c.w, c2, acc.w);
        acc.x = fmaf(d.x, c3, acc.x); acc.y = fmaf(d.y, c3, acc.y);
        acc.z = fmaf(d.z, c3, acc.z); acc.w = fmaf(d.w, c3, acc.w);
    }
    for (; j < end; j++) {
        int s0 = __ldg(g_csr + j);
        float c0 = __ldg(g_ninv_out + s0);
        float4 a = __ldg(x4 + (size_t)s0 * (F / 4) + lane);
        acc.x = fmaf(a.x, c0, acc.x); acc.y = fmaf(a.y, c0, acc.y);
        acc.z = fmaf(a.z, c0, acc.z); acc.w = fmaf(a.w, c0, acc.w);
    }
    ((float4*)g_agg1)[(size_t)v * (F / 4) + lane] = acc;
}

// ---------------------------------------------------------------------------
// Fused: h = relu(agg1 @ W1 * ninv_in + b1); t2 = (h * ninv_out) @ W2
__global__ void __launch_bounds__(256)
k_gemm_fused(const float* __restrict__ W1, const float* __restrict__ b1,
             const float* __restrict__ W2, int n_nodes) {
    __shared__ float sW[64 * F];     // 32 KB (K-half of W1)
    __shared__ float sX[64][64];     // 16 KB (64 rows, K-half)

    int tid = threadIdx.x;
    int cg = tid & 31;
    int rg = tid >> 5;
    int row0 = blockIdx.x * 64;

    float acc[8][4];
#pragma unroll
    for (int i = 0; i < 8; i++)
#pragma unroll
        for (int c = 0; c < 4; c++) acc[i][c] = 0.f;

    for (int half = 0; half < 2; half++) {
        const float4* Wsrc = (const float4*)(W1 + half * 64 * F);
        for (int j = tid; j < 2048; j += 256)
            ((float4*)sW)[j] = __ldg(Wsrc + j);
        for (int j = tid; j < 1024; j += 256) {
            int r = j >> 4, c4 = j & 15;
            int row = row0 + r;
            float4 v = make_float4(0.f, 0.f, 0.f, 0.f);
            if (row < n_nodes)
                v = *((const float4*)(g_agg1 + (size_t)row * F + half * 64) + c4);
            ((float4*)&sX[r][0])[c4] = v;
        }
        __syncthreads();
#pragma unroll
        for (int k4 = 0; k4 < 64; k4 += 4) {
            float4 w0 = ((const float4*)(sW + (k4 + 0) * F))[cg];
            float4 w1 = ((const float4*)(sW + (k4 + 1) * F))[cg];
            float4 w2 = ((const float4*)(sW + (k4 + 2) * F))[cg];
            float4 w3 = ((const float4*)(sW + (k4 + 3) * F))[cg];
#pragma unroll
            for (int i = 0; i < 8; i++) {
                float4 xv = *(const float4*)&sX[rg * 8 + i][k4];
                acc[i][0] = fmaf(xv.x, w0.x, acc[i][0]);
                acc[i][1] = fmaf(xv.x, w0.y, acc[i][1]);
                acc[i][2] = fmaf(xv.x, w0.z, acc[i][2]);
                acc[i][3] = fmaf(xv.x, w0.w, acc[i][3]);
                acc[i][0] = fmaf(xv.y, w1.x, acc[i][0]);
                acc[i][1] = fmaf(xv.y, w1.y, acc[i][1]);
                acc[i][2] = fmaf(xv.y, w1.z, acc[i][2]);
                acc[i][3] = fmaf(xv.y, w1.w, acc[i][3]);
                acc[i][0] = fmaf(xv.z, w2.x, acc[i][0]);
                acc[i][1] = fmaf(xv.z, w2.y, acc[i][1]);
                acc[i][2] = fmaf(xv.z, w2.z, acc[i][2]);
                acc[i][3] = fmaf(xv.z, w2.w, acc[i][3]);
                acc[i][0] = fmaf(xv.w, w3.x, acc[i][0]);
                acc[i][1] = fmaf(xv.w, w3.y, acc[i][1]);
                acc[i][2] = fmaf(xv.w, w3.z, acc[i][2]);
                acc[i][3] = fmaf(xv.w, w3.w, acc[i][3]);
            }
        }
        __syncthreads();
    }

    float w2a[4], w2b[4], bb[4];
#pragma unroll
    for (int c = 0; c < 4; c++) {
        int col = cg * 4 + c;
        bb[c]  = __ldg(b1 + col);
        w2a[c] = __ldg(W2 + col * 2);
        w2b[c] = __ldg(W2 + col * 2 + 1);
    }
#pragma unroll
    for (int i = 0; i < 8; i++) {
        int row = row0 + rg * 8 + i;
        bool valid = row < n_nodes;
        int rr = valid ? row : 0;
        float ni = g_ninv_in[rr];
        float no = g_ninv_out[rr];
        float p0 = 0.f, p1 = 0.f;
#pragma unroll
        for (int c = 0; c < 4; c++) {
            float h = fmaf(acc[i][c], ni, bb[c]);
            h = fmaxf(h, 0.f) * no;
            p0 = fmaf(h, w2a[c], p0);
            p1 = fmaf(h, w2b[c], p1);
        }
#pragma unroll
        for (int off = 16; off; off >>= 1) {
            p0 += __shfl_xor_sync(0xffffffffu, p0, off);
            p1 += __shfl_xor_sync(0xffffffffu, p1, off);
        }
        if (cg == 0 && valid) {
            g_t2[row * 2]     = p0;
            g_t2[row * 2 + 1] = p1;
        }
    }
}

// ---------------------------------------------------------------------------
// Layer-2 pull: one warp per dst node.
__global__ void k_pull2(const float* __restrict__ b2, float* __restrict__ out,
                        int n_nodes) {
    int v = (blockIdx.x * blockDim.x + threadIdx.x) >> 5;
    int lane = threadIdx.x & 31;
    if (v >= n_nodes) return;
    int beg = g_rowoff[v];
    int end = beg + g_degi[v];
    float px = 0.f, py = 0.f;
    for (int j = beg + lane; j < end; j += 32) {
        int s = __ldg(g_csr + j);
        float2 t = ((const float2*)g_t2)[s];
        px += t.x; py += t.y;
    }
#pragma unroll
    for (int off = 16; off; off >>= 1) {
        px += __shfl_xor_sync(0xffffffffu, px, off);
        py += __shfl_xor_sync(0xffffffffu, py, off);
    }
    if (lane == 0) {
        float ni = g_ninv_in[v];
        float2 o;
        o.x = fmaf(px, ni, __ldg(b2));
        o.y = fmaf(py, ni, __ldg(b2 + 1));
        ((float2*)out)[v] = o;
    }
}

// ---------------------------------------------------------------------------
extern "C" void kernel_launch(void* const* d_in, const int* in_sizes, int n_in,
                              void* d_out, int out_size) {
    const float* x  = (const float*)d_in[0];
    const float* W1 = (const float*)d_in[1];
    const float* b1 = (const float*)d_in[2];
    const float* W2 = (const float*)d_in[3];
    const float* b2 = (const float*)d_in[4];
    const int* src  = (const int*)d_in[5];
    const int* dst  = (const int*)d_in[6];
    int n_nodes = in_sizes[0] / F;
    int n_edges = in_sizes[5];

    int nbN = (n_nodes + 255) / 256;
    int nbE = (n_edges + 255) / 256;
    int nbW = (n_nodes * 32 + 255) / 256;                // warp per node
    int nbS = (n_nodes + SCAN_CHUNK - 1) / SCAN_CHUNK;   // scan blocks

    k_zero<<<nbN, 256>>>(n_nodes);
    k_deg<<<nbE, 256>>>(src, dst, n_edges);
    k_ninv<<<nbN, 256>>>(n_nodes);
    k_scan1<<<nbS, SCAN_CHUNK>>>(n_nodes);
    k_scan2<<<1, MAX_SCAN_BLOCKS>>>(nbS);
    k_scan3<<<nbS, SCAN_CHUNK>>>(n_nodes);
    k_scatter<<<nbE, 256>>>(src, dst, n_edges);
    k_pull1<<<nbW, 256>>>(x, n_nodes);
    k_gemm_fused<<<(n_nodes + 63) / 64, 256>>>(W1, b1, W2, n_nodes);
    k_pull2<<<nbW, 256>>>(b2, (float*)d_out, n_nodes);
}